// round 2
// baseline (speedup 1.0000x reference)
#include <cuda_runtime.h>
#include <math.h>

#define S_LEN 2048
#define DDIM  128
#define BM    64
#define BN    64
#define NTHREADS 256

// smem layout (floats):
//  Qt: [128][64]  k-major, XOR-quad swizzled
//  Kt: [128][64]  k-major, XOR-quad swizzled
//  Pt: [64][64]   j-major, XOR-quad swizzled
//  Vs: [64][128]  row-major
#define QT_OFF 0
#define KT_OFF (128*64)
#define PT_OFF (KT_OFF + 128*64)
#define VS_OFF (PT_OFF + 64*64)
#define SMEM_FLOATS (VS_OFF + 64*128)
#define SMEM_BYTES  (SMEM_FLOATS * 4)

__global__ __launch_bounds__(NTHREADS, 1)
void attn_kernel(const float* __restrict__ Q, const float* __restrict__ K,
                 const float* __restrict__ V, float* __restrict__ O) {
    extern __shared__ float smem[];
    float* Qt = smem + QT_OFF;
    float* Kt = smem + KT_OFF;
    float* Pt = smem + PT_OFF;
    float* Vs = smem + VS_OFF;

    const int qt    = blockIdx.x;
    const int b     = blockIdx.y;
    const int qbase = qt * BM;
    const int tid   = threadIdx.x;
    const int tx    = tid & 15;   // 0..15
    const int ty    = tid >> 4;   // 0..15

    const float* Qg = Q + (size_t)b * S_LEN * DDIM;
    const float* Kg = K + (size_t)b * S_LEN * DDIM;
    const float* Vg = V + (size_t)b * S_LEN * DDIM;
    float*       Og = O + (size_t)b * S_LEN * DDIM;

    // ---- load Q tile, transposed k-major with XOR-quad swizzle ----
    for (int i = tid; i < BM * DDIM; i += NTHREADS) {
        int m = i >> 7;         // tile row
        int k = i & 127;        // dim
        float v = Qg[(qbase + m) * DDIM + k];
        Qt[k * 64 + ((((m >> 2) ^ (k & 15)) << 2) | (m & 3))] = v;
    }

    float o[32];
    #pragma unroll
    for (int i = 0; i < 32; i++) o[i] = 0.f;
    float mrow[4], lrow[4];
    #pragma unroll
    for (int r = 0; r < 4; r++) { mrow[r] = -INFINITY; lrow[r] = 0.f; }

    const float qk_scale = 0.0883883476483184405f;   // 1/sqrt(128)

    const int ntiles = qt + 1;                       // causal: only tiles with valid keys
    for (int t = 0; t < ntiles; t++) {
        const int kb = t * BN;
        __syncthreads();   // previous iteration done with Kt/Vs/Pt

        // ---- load K tile (transposed+swizzled) and V tile (row-major) ----
        for (int i = tid; i < BN * DDIM; i += NTHREADS) {
            int n = i >> 7;
            int k = i & 127;
            Kt[k * 64 + ((((n >> 2) ^ (k & 15)) << 2) | (n & 3))] = Kg[(kb + n) * DDIM + k];
        }
        for (int i = tid * 4; i < BN * DDIM; i += NTHREADS * 4) {
            *(float4*)&Vs[i] = *(const float4*)&Vg[kb * DDIM + i];
        }
        __syncthreads();

        // ---- S = Q K^T  (64x64x128, 4x4 micro-tile) ----
        float s[4][4];
        #pragma unroll
        for (int r = 0; r < 4; r++)
            #pragma unroll
            for (int c = 0; c < 4; c++) s[r][c] = 0.f;

        #pragma unroll 4
        for (int k = 0; k < DDIM; k++) {
            float4 af = *(float4*)&Qt[k * 64 + ((ty ^ (k & 15)) << 2)];
            float4 bf = *(float4*)&Kt[k * 64 + ((tx ^ (k & 15)) << 2)];
            float av[4] = {af.x, af.y, af.z, af.w};
            float bv[4] = {bf.x, bf.y, bf.z, bf.w};
            #pragma unroll
            for (int r = 0; r < 4; r++)
                #pragma unroll
                for (int c = 0; c < 4; c++)
                    s[r][c] += av[r] * bv[c];
        }

        // ---- scale + causal mask (only diagonal tile needs it) ----
        const bool diag = (kb + BN > qbase);
        #pragma unroll
        for (int r = 0; r < 4; r++) {
            int grow = qbase + ty * 4 + r;
            #pragma unroll
            for (int c = 0; c < 4; c++) {
                int gcol = kb + tx * 4 + c;
                float v = s[r][c] * qk_scale;
                if (diag && gcol > grow) v = -1e9f;   // matches reference MASK_FILL
                s[r][c] = v;
            }
        }

        // ---- online softmax (row reductions over the 16 tx-threads = half warp) ----
        float alpha[4];
        #pragma unroll
        for (int r = 0; r < 4; r++) {
            float mx = fmaxf(fmaxf(s[r][0], s[r][1]), fmaxf(s[r][2], s[r][3]));
            #pragma unroll
            for (int off = 8; off >= 1; off >>= 1)
                mx = fmaxf(mx, __shfl_xor_sync(0xffffffffu, mx, off, 16));
            float mnew = fmaxf(mrow[r], mx);
            alpha[r] = __expf(mrow[r] - mnew);        // first tile: exp(-inf)=0
            mrow[r] = mnew;
            float sum = 0.f;
            #pragma unroll
            for (int c = 0; c < 4; c++) {
                float p = __expf(s[r][c] - mnew);     // masked: exp(~-1e9)=0 exactly
                s[r][c] = p;
                sum += p;
            }
            #pragma unroll
            for (int off = 8; off >= 1; off >>= 1)
                sum += __shfl_xor_sync(0xffffffffu, sum, off, 16);
            lrow[r] = lrow[r] * alpha[r] + sum;
        }

        // ---- rescale running O ----
        #pragma unroll
        for (int r = 0; r < 4; r++)
            #pragma unroll
            for (int c = 0; c < 8; c++)
                o[r * 8 + c] *= alpha[r];

        // ---- store P transposed+swizzled ----
        #pragma unroll
        for (int c = 0; c < 4; c++) {
            int j = tx * 4 + c;
            #pragma unroll
            for (int r = 0; r < 4; r++)
                Pt[j * 64 + (((ty ^ (j & 15)) << 2) | r)] = s[r][c];
        }
        __syncthreads();

        // ---- O += P V  (64x128x64, 4x8 micro-tile; cols split into two halves) ----
        #pragma unroll 2
        for (int j = 0; j < BN; j++) {
            float4 af = *(float4*)&Pt[j * 64 + ((ty ^ (j & 15)) << 2)];
            float4 b0 = *(float4*)&Vs[j * DDIM + tx * 4];
            float4 b1 = *(float4*)&Vs[j * DDIM + 64 + tx * 4];
            float av[4] = {af.x, af.y, af.z, af.w};
            float bv[8] = {b0.x, b0.y, b0.z, b0.w, b1.x, b1.y, b1.z, b1.w};
            #pragma unroll
            for (int r = 0; r < 4; r++)
                #pragma unroll
                for (int c = 0; c < 8; c++)
                    o[r * 8 + c] += av[r] * bv[c];
        }
    }

    // ---- epilogue: normalize and store ----
    #pragma unroll
    for (int r = 0; r < 4; r++) {
        float inv = 1.f / lrow[r];
        int grow = qbase + ty * 4 + r;
        float4 v0 = make_float4(o[r*8+0]*inv, o[r*8+1]*inv, o[r*8+2]*inv, o[r*8+3]*inv);
        float4 v1 = make_float4(o[r*8+4]*inv, o[r*8+5]*inv, o[r*8+6]*inv, o[r*8+7]*inv);
        *(float4*)&Og[grow * DDIM + tx * 4]      = v0;
        *(float4*)&Og[grow * DDIM + 64 + tx * 4] = v1;
    }
}

extern "C" void kernel_launch(void* const* d_in, const int* in_sizes, int n_in,
                              void* d_out, int out_size) {
    const float* Q = (const float*)d_in[0];
    const float* K = (const float*)d_in[1];
    const float* V = (const float*)d_in[2];
    float*       O = (float*)d_out;

    int B = in_sizes[0] / (S_LEN * DDIM);

    cudaFuncSetAttribute(attn_kernel, cudaFuncAttributeMaxDynamicSharedMemorySize, SMEM_BYTES);

    dim3 grid(S_LEN / BM, B);
    attn_kernel<<<grid, NTHREADS, SMEM_BYTES>>>(Q, K, V, O);
}

// round 4
// speedup vs baseline: 2.6725x; 2.6725x over previous
#include <cuda_runtime.h>
#include <cuda_bf16.h>
#include <stdint.h>
#include <math.h>

#define S_LEN 2048
#define DDIM  128
#define BM 128
#define BN 64
#define NT 256

// smem byte offsets: 256B-row tiles (Q,K,V) and 128B-row tiles (P)
#define QH_O 0
#define QL_O 32768
#define KH_O 65536
#define KL_O 81920
#define VH_O 98304
#define VL_O 114688
#define PH_O 131072
#define PL_O 147456
#define SMEM_BYTES 163840

static __device__ __forceinline__ uint32_t smem_u32(const void* p) {
    uint32_t a;
    asm("{ .reg .u64 t; cvta.to.shared.u64 t, %1; cvt.u32.u64 %0, t; }" : "=r"(a) : "l"(p));
    return a;
}
static __device__ __forceinline__ void ldsm_x4(uint32_t r[4], uint32_t a) {
    asm volatile("ldmatrix.sync.aligned.m8n8.x4.shared.b16 {%0,%1,%2,%3}, [%4];"
                 : "=r"(r[0]), "=r"(r[1]), "=r"(r[2]), "=r"(r[3]) : "r"(a));
}
static __device__ __forceinline__ void ldsm_x2(uint32_t r[2], uint32_t a) {
    asm volatile("ldmatrix.sync.aligned.m8n8.x2.shared.b16 {%0,%1}, [%2];"
                 : "=r"(r[0]), "=r"(r[1]) : "r"(a));
}
static __device__ __forceinline__ void ldsm_x2t(uint32_t r[2], uint32_t a) {
    asm volatile("ldmatrix.sync.aligned.m8n8.x2.trans.shared.b16 {%0,%1}, [%2];"
                 : "=r"(r[0]), "=r"(r[1]) : "r"(a));
}
static __device__ __forceinline__ void mma16816(float c[4], const uint32_t a[4], const uint32_t b[2]) {
    asm volatile("mma.sync.aligned.m16n8k16.row.col.f32.bf16.bf16.f32 "
                 "{%0,%1,%2,%3}, {%4,%5,%6,%7}, {%8,%9}, {%0,%1,%2,%3};"
                 : "+f"(c[0]), "+f"(c[1]), "+f"(c[2]), "+f"(c[3])
                 : "r"(a[0]), "r"(a[1]), "r"(a[2]), "r"(a[3]), "r"(b[0]), "r"(b[1]));
}
// split fp32 pair into (hi bf16x2, lo bf16x2)
static __device__ __forceinline__ void split2(float x, float y, uint32_t& h, uint32_t& l) {
    __nv_bfloat16 hx = __float2bfloat16_rn(x), hy = __float2bfloat16_rn(y);
    h = ((uint32_t)__bfloat16_as_ushort(hy) << 16) | __bfloat16_as_ushort(hx);
    __nv_bfloat16 lx = __float2bfloat16_rn(x - __bfloat162float(hx));
    __nv_bfloat16 ly = __float2bfloat16_rn(y - __bfloat162float(hy));
    l = ((uint32_t)__bfloat16_as_ushort(ly) << 16) | __bfloat16_as_ushort(lx);
}

__global__ __launch_bounds__(NT, 1)
void attn_hmma(const float* __restrict__ Q, const float* __restrict__ K,
               const float* __restrict__ V, float* __restrict__ O) {
    extern __shared__ char sm[];
    const uint32_t sb = smem_u32(sm);
    const int tid  = threadIdx.x;
    const int lane = tid & 31;
    const int w    = tid >> 5;
    const int qt    = gridDim.x - 1 - blockIdx.x;   // heavy CTAs first
    const int b     = blockIdx.y;
    const int qbase = qt * BM;
    const int ntile = 2 * qt + 2;
    const int m0    = w * 16;

    const float* Qg = Q + (size_t)b * S_LEN * DDIM;
    const float* Kg = K + (size_t)b * S_LEN * DDIM;
    const float* Vg = V + (size_t)b * S_LEN * DDIM;
    float*       Og = O + (size_t)b * S_LEN * DDIM;

    // ldmatrix lane decodes
    const int aR   = m0 + (lane & 7) + ((lane & 8) ? 8 : 0);   // A row (Q / P)
    const int aK   = (lane & 16) ? 16 : 0;                      // A k-halve byte offset
    const int aXor = (aR & 7) << 4;
    const int lb   = lane & 15;
    const int bR   = lb & 7;                                    // K row within n-tile
    const int bK   = (lb & 8) ? 16 : 0;
    const int bXor = bR << 4;
    const int vR   = lb;                                        // V row within k16 group
    const int vXor = (vR & 7) << 4;

    // ---- Q -> Qh/Ql smem (rows 256B, swizzled) ----
    for (int i = tid; i < BM * 32; i += NT) {
        int row = i >> 5, k4 = i & 31;
        float4 q = ((const float4*)Qg)[(size_t)(qbase + row) * 32 + k4];
        uint32_t h0, l0, h1, l1;
        split2(q.x, q.y, h0, l0); split2(q.z, q.w, h1, l1);
        uint32_t off = (uint32_t)(row * 256 + ((k4 * 8) ^ ((row & 7) << 4)));
        *(uint2*)(sm + QH_O + off) = make_uint2(h0, h1);
        *(uint2*)(sm + QL_O + off) = make_uint2(l0, l1);
    }

    float o[16][4];
    #pragma unroll
    for (int n = 0; n < 16; n++)
        #pragma unroll
        for (int i = 0; i < 4; i++) o[n][i] = 0.f;
    float mr0 = -INFINITY, mr1 = -INFINITY, l0r = 0.f, l1r = 0.f;

    const int r0gl = qbase + m0 + (lane >> 2);
    const int r1gl = r0gl + 8;
    const int cb   = (lane & 3) * 2;
    const float SCALE = 0.0883883476483184405f;   // 1/sqrt(128)

    for (int t = 0; t < ntile; t++) {
        const int kb = t * BN;
        __syncthreads();   // prior tile's MMA reads of K/V done
        // ---- K,V tiles -> split bf16 smem ----
        for (int i = tid; i < BN * 32; i += NT) {
            int row = i >> 5, k4 = i & 31;
            uint32_t off = (uint32_t)(row * 256 + ((k4 * 8) ^ ((row & 7) << 4)));
            float4 kf = ((const float4*)Kg)[(size_t)(kb + row) * 32 + k4];
            uint32_t h0, l0, h1, l1;
            split2(kf.x, kf.y, h0, l0); split2(kf.z, kf.w, h1, l1);
            *(uint2*)(sm + KH_O + off) = make_uint2(h0, h1);
            *(uint2*)(sm + KL_O + off) = make_uint2(l0, l1);
            float4 vf = ((const float4*)Vg)[(size_t)(kb + row) * 32 + k4];
            split2(vf.x, vf.y, h0, l0); split2(vf.z, vf.w, h1, l1);
            *(uint2*)(sm + VH_O + off) = make_uint2(h0, h1);
            *(uint2*)(sm + VL_O + off) = make_uint2(l0, l1);
        }
        __syncthreads();

        // ---- S = Q K^T : pass (Qh+Ql)·Kh then Qh·Kl ----
        float cs[8][4];
        #pragma unroll
        for (int n = 0; n < 8; n++)
            #pragma unroll
            for (int i = 0; i < 4; i++) cs[n][i] = 0.f;

        #pragma unroll
        for (int k = 0; k < 8; k++) {
            uint32_t ah[4], al[4];
            ldsm_x4(ah, sb + QH_O + aR * 256 + ((k * 32 + aK) ^ aXor));
            ldsm_x4(al, sb + QL_O + aR * 256 + ((k * 32 + aK) ^ aXor));
            #pragma unroll
            for (int n = 0; n < 8; n++) {
                uint32_t bf[2];
                ldsm_x2(bf, sb + KH_O + (n * 8 + bR) * 256 + ((k * 32 + bK) ^ bXor));
                mma16816(cs[n], ah, bf);
                mma16816(cs[n], al, bf);
            }
        }
        #pragma unroll
        for (int k = 0; k < 8; k++) {
            uint32_t ah[4];
            ldsm_x4(ah, sb + QH_O + aR * 256 + ((k * 32 + aK) ^ aXor));
            #pragma unroll
            for (int n = 0; n < 8; n++) {
                uint32_t bf[2];
                ldsm_x2(bf, sb + KL_O + (n * 8 + bR) * 256 + ((k * 32 + bK) ^ bXor));
                mma16816(cs[n], ah, bf);
            }
        }

        // ---- softmax (2 rows per thread, quad reductions) ----
        float mx0 = -INFINITY, mx1 = -INFINITY;
        #pragma unroll
        for (int n = 0; n < 8; n++) {
            int jg = kb + n * 8 + cb;
            float x0 = cs[n][0] * SCALE; if (jg > r0gl)     x0 = -1e9f;
            float x1 = cs[n][1] * SCALE; if (jg + 1 > r0gl) x1 = -1e9f;
            float x2 = cs[n][2] * SCALE; if (jg > r1gl)     x2 = -1e9f;
            float x3 = cs[n][3] * SCALE; if (jg + 1 > r1gl) x3 = -1e9f;
            cs[n][0] = x0; cs[n][1] = x1; cs[n][2] = x2; cs[n][3] = x3;
            mx0 = fmaxf(mx0, fmaxf(x0, x1));
            mx1 = fmaxf(mx1, fmaxf(x2, x3));
        }
        mx0 = fmaxf(mx0, __shfl_xor_sync(0xffffffffu, mx0, 1));
        mx0 = fmaxf(mx0, __shfl_xor_sync(0xffffffffu, mx0, 2));
        mx1 = fmaxf(mx1, __shfl_xor_sync(0xffffffffu, mx1, 1));
        mx1 = fmaxf(mx1, __shfl_xor_sync(0xffffffffu, mx1, 2));
        float mn0 = fmaxf(mr0, mx0), mn1 = fmaxf(mr1, mx1);
        float al0 = __expf(mr0 - mn0), al1 = __expf(mr1 - mn1);
        mr0 = mn0; mr1 = mn1;

        const int pr0 = m0 + (lane >> 2);
        const int pXor = (pr0 & 7) << 4;
        float s0 = 0.f, s1 = 0.f;
        #pragma unroll
        for (int n = 0; n < 8; n++) {
            float p0 = __expf(cs[n][0] - mn0);
            float p1 = __expf(cs[n][1] - mn0);
            float p2 = __expf(cs[n][2] - mn1);
            float p3 = __expf(cs[n][3] - mn1);
            s0 += p0 + p1; s1 += p2 + p3;
            uint32_t h, l;
            uint32_t off0 = (uint32_t)(pr0 * 128 + ((n * 16 + (lane & 3) * 4) ^ pXor));
            split2(p0, p1, h, l);
            *(uint32_t*)(sm + PH_O + off0) = h;
            *(uint32_t*)(sm + PL_O + off0) = l;
            uint32_t off1 = off0 + 8 * 128;
            split2(p2, p3, h, l);
            *(uint32_t*)(sm + PH_O + off1) = h;
            *(uint32_t*)(sm + PL_O + off1) = l;
        }
        s0 += __shfl_xor_sync(0xffffffffu, s0, 1);
        s0 += __shfl_xor_sync(0xffffffffu, s0, 2);
        s1 += __shfl_xor_sync(0xffffffffu, s1, 1);
        s1 += __shfl_xor_sync(0xffffffffu, s1, 2);
        l0r = l0r * al0 + s0;
        l1r = l1r * al1 + s1;

        // rescale running O
        #pragma unroll
        for (int n = 0; n < 16; n++) {
            o[n][0] *= al0; o[n][1] *= al0;
            o[n][2] *= al1; o[n][3] *= al1;
        }
        __syncwarp();   // P rows are warp-private: warp-level visibility suffices

        // ---- O += P V : pass (Ph+Pl)·Vh then Ph·Vl ----
        #pragma unroll
        for (int k = 0; k < 4; k++) {
            uint32_t ph[4], pl[4];
            ldsm_x4(ph, sb + PH_O + aR * 128 + ((k * 32 + aK) ^ aXor));
            ldsm_x4(pl, sb + PL_O + aR * 128 + ((k * 32 + aK) ^ aXor));
            #pragma unroll
            for (int n = 0; n < 16; n++) {
                uint32_t bf[2];
                ldsm_x2t(bf, sb + VH_O + (k * 16 + vR) * 256 + ((n * 16) ^ vXor));
                mma16816(o[n], ph, bf);
                mma16816(o[n], pl, bf);
            }
        }
        #pragma unroll
        for (int k = 0; k < 4; k++) {
            uint32_t ph[4];
            ldsm_x4(ph, sb + PH_O + aR * 128 + ((k * 32 + aK) ^ aXor));
            #pragma unroll
            for (int n = 0; n < 16; n++) {
                uint32_t bf[2];
                ldsm_x2t(bf, sb + VL_O + (k * 16 + vR) * 256 + ((n * 16) ^ vXor));
                mma16816(o[n], ph, bf);
            }
        }
    }

    // ---- epilogue ----
    const float inv0 = 1.f / l0r, inv1 = 1.f / l1r;
    #pragma unroll
    for (int n = 0; n < 16; n++) {
        int col = n * 8 + cb;
        *(float2*)(Og + (size_t)r0gl * DDIM + col) = make_float2(o[n][0] * inv0, o[n][1] * inv0);
        *(float2*)(Og + (size_t)r1gl * DDIM + col) = make_float2(o[n][2] * inv1, o[n][3] * inv1);
    }
}

extern "C" void kernel_launch(void* const* d_in, const int* in_sizes, int n_in,
                              void* d_out, int out_size) {
    const float* Q = (const float*)d_in[0];
    const float* K = (const float*)d_in[1];
    const float* V = (const float*)d_in[2];
    float*       O = (float*)d_out;
    int B = in_sizes[0] / (S_LEN * DDIM);
    cudaFuncSetAttribute(attn_hmma, cudaFuncAttributeMaxDynamicSharedMemorySize, SMEM_BYTES);
    dim3 grid(S_LEN / BM, B);
    attn_hmma<<<grid, NT, SMEM_BYTES>>>(Q, K, V, O);
}

// round 6
// speedup vs baseline: 2.9952x; 1.1207x over previous
#include <cuda_runtime.h>
#include <cuda_bf16.h>
#include <stdint.h>
#include <math.h>

#define S_LEN 2048
#define DDIM  128
#define BM 128
#define BN 64
#define NT 256

// smem map: bf16 K/V tiles + raw fp32 staging
#define KH_O 0
#define KL_O 16384
#define VH_O 32768
#define VL_O 49152
#define STK_O 65536
#define STV_O 98304
#define SMEM_BYTES 131072
// Q bf16 staging (prologue only) overlays KH..KL (Qh) and VH..VL (Ql)
#define QH_O 0
#define QL_O 32768

static __device__ __forceinline__ uint32_t smem_u32(const void* p) {
    uint32_t a;
    asm("{ .reg .u64 t; cvta.to.shared.u64 t, %1; cvt.u32.u64 %0, t; }" : "=r"(a) : "l"(p));
    return a;
}
static __device__ __forceinline__ void ldsm_x4(uint32_t r[4], uint32_t a) {
    asm volatile("ldmatrix.sync.aligned.m8n8.x4.shared.b16 {%0,%1,%2,%3}, [%4];"
                 : "=r"(r[0]), "=r"(r[1]), "=r"(r[2]), "=r"(r[3]) : "r"(a));
}
static __device__ __forceinline__ void ldsm_x2(uint32_t r[2], uint32_t a) {
    asm volatile("ldmatrix.sync.aligned.m8n8.x2.shared.b16 {%0,%1}, [%2];"
                 : "=r"(r[0]), "=r"(r[1]) : "r"(a));
}
static __device__ __forceinline__ void ldsm_x2t(uint32_t r[2], uint32_t a) {
    asm volatile("ldmatrix.sync.aligned.m8n8.x2.trans.shared.b16 {%0,%1}, [%2];"
                 : "=r"(r[0]), "=r"(r[1]) : "r"(a));
}
static __device__ __forceinline__ void mma16816(float c[4], const uint32_t a[4], const uint32_t b[2]) {
    asm volatile("mma.sync.aligned.m16n8k16.row.col.f32.bf16.bf16.f32 "
                 "{%0,%1,%2,%3}, {%4,%5,%6,%7}, {%8,%9}, {%0,%1,%2,%3};"
                 : "+f"(c[0]), "+f"(c[1]), "+f"(c[2]), "+f"(c[3])
                 : "r"(a[0]), "r"(a[1]), "r"(a[2]), "r"(a[3]), "r"(b[0]), "r"(b[1]));
}
static __device__ __forceinline__ void cp16(uint32_t dst, const void* src) {
    asm volatile("cp.async.cg.shared.global [%0], [%1], 16;" :: "r"(dst), "l"(src));
}
static __device__ __forceinline__ void cp_commit() {
    asm volatile("cp.async.commit_group;" ::: "memory");
}
static __device__ __forceinline__ void cp_wait0() {
    asm volatile("cp.async.wait_group 0;" ::: "memory");
}
static __device__ __forceinline__ void split2(float x, float y, uint32_t& h, uint32_t& l) {
    __nv_bfloat16 hx = __float2bfloat16_rn(x), hy = __float2bfloat16_rn(y);
    h = ((uint32_t)__bfloat16_as_ushort(hy) << 16) | __bfloat16_as_ushort(hx);
    __nv_bfloat16 lx = __float2bfloat16_rn(x - __bfloat162float(hx));
    __nv_bfloat16 ly = __float2bfloat16_rn(y - __bfloat162float(hy));
    l = ((uint32_t)__bfloat16_as_ushort(ly) << 16) | __bfloat16_as_ushort(lx);
}

__global__ __launch_bounds__(NT, 1)
void attn_hmma(const float* __restrict__ Q, const float* __restrict__ K,
               const float* __restrict__ V, float* __restrict__ O) {
    extern __shared__ char sm[];
    const uint32_t sb = smem_u32(sm);
    const int tid  = threadIdx.x;
    const int lane = tid & 31;
    const int w    = tid >> 5;
    const int qt    = gridDim.x - 1 - blockIdx.x;   // heavy CTAs first
    const int b     = blockIdx.y;
    const int qbase = qt * BM;
    const int ntile = 2 * qt + 2;
    const int m0    = w * 16;

    const float* Qg = Q + (size_t)b * S_LEN * DDIM;
    const float* Kg = K + (size_t)b * S_LEN * DDIM;
    const float* Vg = V + (size_t)b * S_LEN * DDIM;
    float*       Og = O + (size_t)b * S_LEN * DDIM;

    // ldmatrix lane decodes
    const int aR   = m0 + (lane & 15);
    const int aK   = (lane & 16) ? 16 : 0;
    const int aXor = (aR & 7) << 4;
    const int lb   = lane & 15;
    const int bR   = lb & 7;
    const int bK   = (lb & 8) ? 16 : 0;
    const int bXor = bR << 4;
    const int vR   = lb;
    const int vXor = (vR & 7) << 4;

    // ---- prologue: Q -> bf16 smem staging -> registers ----
    for (int i = tid; i < BM * 32; i += NT) {
        int row = i >> 5, k4 = i & 31;
        float4 q = ((const float4*)Qg)[(size_t)(qbase + row) * 32 + k4];
        uint32_t h0, l0, h1, l1;
        split2(q.x, q.y, h0, l0); split2(q.z, q.w, h1, l1);
        uint32_t off = (uint32_t)(row * 256 + ((k4 * 8) ^ ((row & 7) << 4)));
        *(uint2*)(sm + QH_O + off) = make_uint2(h0, h1);
        *(uint2*)(sm + QL_O + off) = make_uint2(l0, l1);
    }
    __syncthreads();
    uint32_t qh[8][4], ql[8][4];
    #pragma unroll
    for (int kk = 0; kk < 8; kk++) {
        ldsm_x4(qh[kk], sb + QH_O + aR * 256 + ((kk * 32 + aK) ^ aXor));
        ldsm_x4(ql[kk], sb + QL_O + aR * 256 + ((kk * 32 + aK) ^ aXor));
    }
    __syncthreads();   // done reading Q staging; K/V bufs may be written

    // ---- stage tile 0 and convert ----
    {
        #pragma unroll
        for (int j = 0; j < 8; j++) {
            int i = tid + j * NT;
            cp16(sb + STK_O + i * 16, (const void*)(Kg + (size_t)i * 4));
            cp16(sb + STV_O + i * 16, (const void*)(Vg + (size_t)i * 4));
        }
        cp_commit();
        cp_wait0();
        __syncthreads();
        for (int i = tid; i < BN * 32; i += NT) {
            int row = i >> 5, k4 = i & 31;
            uint32_t off = (uint32_t)(row * 256 + ((k4 * 8) ^ ((row & 7) << 4)));
            float4 kf = *(const float4*)(sm + STK_O + i * 16);
            uint32_t h0, l0, h1, l1;
            split2(kf.x, kf.y, h0, l0); split2(kf.z, kf.w, h1, l1);
            *(uint2*)(sm + KH_O + off) = make_uint2(h0, h1);
            *(uint2*)(sm + KL_O + off) = make_uint2(l0, l1);
            float4 vf = *(const float4*)(sm + STV_O + i * 16);
            split2(vf.x, vf.y, h0, l0); split2(vf.z, vf.w, h1, l1);
            *(uint2*)(sm + VH_O + off) = make_uint2(h0, h1);
            *(uint2*)(sm + VL_O + off) = make_uint2(l0, l1);
        }
        __syncthreads();
    }

    float o[16][4];
    #pragma unroll
    for (int n = 0; n < 16; n++)
        #pragma unroll
        for (int i = 0; i < 4; i++) o[n][i] = 0.f;
    float mr0 = -INFINITY, mr1 = -INFINITY, l0r = 0.f, l1r = 0.f;

    const int r0gl = qbase + m0 + (lane >> 2);
    const int r1gl = r0gl + 8;
    const int cb   = (lane & 3) * 2;
    const float SCALE = 0.0883883476483184405f;

    for (int t = 0; t < ntile; t++) {
        const int kb = t * BN;
        const bool more = (t + 1 < ntile);
        // ---- prefetch next raw K/V tile into staging ----
        if (more) {
            const float* Kn = Kg + (size_t)(kb + BN) * DDIM;
            const float* Vn = Vg + (size_t)(kb + BN) * DDIM;
            #pragma unroll
            for (int j = 0; j < 8; j++) {
                int i = tid + j * NT;
                cp16(sb + STK_O + i * 16, (const void*)(Kn + (size_t)i * 4));
                cp16(sb + STV_O + i * 16, (const void*)(Vn + (size_t)i * 4));
            }
            cp_commit();
        }

        // ---- S = Q K^T (h*h + l*h + h*l) ----
        float cs[8][4];
        #pragma unroll
        for (int n = 0; n < 8; n++)
            #pragma unroll
            for (int i = 0; i < 4; i++) cs[n][i] = 0.f;

        #pragma unroll
        for (int kk = 0; kk < 8; kk++) {
            #pragma unroll
            for (int n = 0; n < 8; n++) {
                uint32_t bh[2], bl[2];
                ldsm_x2(bh, sb + KH_O + (n * 8 + bR) * 256 + ((kk * 32 + bK) ^ bXor));
                mma16816(cs[n], qh[kk], bh);
                mma16816(cs[n], ql[kk], bh);
                ldsm_x2(bl, sb + KL_O + (n * 8 + bR) * 256 + ((kk * 32 + bK) ^ bXor));
                mma16816(cs[n], qh[kk], bl);
            }
        }

        // ---- softmax (register-only) ----
        float mx0 = -INFINITY, mx1 = -INFINITY;
        #pragma unroll
        for (int n = 0; n < 8; n++) {
            int jg = kb + n * 8 + cb;
            float x0 = cs[n][0] * SCALE; if (jg > r0gl)     x0 = -1e9f;
            float x1 = cs[n][1] * SCALE; if (jg + 1 > r0gl) x1 = -1e9f;
            float x2 = cs[n][2] * SCALE; if (jg > r1gl)     x2 = -1e9f;
            float x3 = cs[n][3] * SCALE; if (jg + 1 > r1gl) x3 = -1e9f;
            cs[n][0] = x0; cs[n][1] = x1; cs[n][2] = x2; cs[n][3] = x3;
            mx0 = fmaxf(mx0, fmaxf(x0, x1));
            mx1 = fmaxf(mx1, fmaxf(x2, x3));
        }
        mx0 = fmaxf(mx0, __shfl_xor_sync(0xffffffffu, mx0, 1));
        mx0 = fmaxf(mx0, __shfl_xor_sync(0xffffffffu, mx0, 2));
        mx1 = fmaxf(mx1, __shfl_xor_sync(0xffffffffu, mx1, 1));
        mx1 = fmaxf(mx1, __shfl_xor_sync(0xffffffffu, mx1, 2));
        float mn0 = fmaxf(mr0, mx0), mn1 = fmaxf(mr1, mx1);
        float al0 = __expf(mr0 - mn0), al1 = __expf(mr1 - mn1);
        mr0 = mn0; mr1 = mn1;

        float s0 = 0.f, s1 = 0.f;
        uint32_t ph[4][4], pl[4][4];   // PV A-fragments, straight from registers
        #pragma unroll
        for (int n = 0; n < 8; n++) {
            float p0 = __expf(cs[n][0] - mn0);
            float p1 = __expf(cs[n][1] - mn0);
            float p2 = __expf(cs[n][2] - mn1);
            float p3 = __expf(cs[n][3] - mn1);
            s0 += p0 + p1; s1 += p2 + p3;
            int g = n >> 1, hi = (n & 1) * 2;
            uint32_t h, l;
            split2(p0, p1, h, l);
            ph[g][hi] = h;     pl[g][hi] = l;
            split2(p2, p3, h, l);
            ph[g][hi + 1] = h; pl[g][hi + 1] = l;
        }
        s0 += __shfl_xor_sync(0xffffffffu, s0, 1);
        s0 += __shfl_xor_sync(0xffffffffu, s0, 2);
        s1 += __shfl_xor_sync(0xffffffffu, s1, 1);
        s1 += __shfl_xor_sync(0xffffffffu, s1, 2);
        l0r = l0r * al0 + s0;
        l1r = l1r * al1 + s1;

        #pragma unroll
        for (int n = 0; n < 16; n++) {
            o[n][0] *= al0; o[n][1] *= al0;
            o[n][2] *= al1; o[n][3] *= al1;
        }

        // ---- O += P V (h*h + l*h + h*l) ----
        #pragma unroll
        for (int g = 0; g < 4; g++) {
            #pragma unroll
            for (int n = 0; n < 16; n++) {
                uint32_t bh[2], bl[2];
                ldsm_x2t(bh, sb + VH_O + (g * 16 + vR) * 256 + ((n * 16) ^ vXor));
                mma16816(o[n], ph[g], bh);
                mma16816(o[n], pl[g], bh);
                ldsm_x2t(bl, sb + VL_O + (g * 16 + vR) * 256 + ((n * 16) ^ vXor));
                mma16816(o[n], ph[g], bl);
            }
        }

        // ---- convert staged tile -> bf16 bufs ----
        if (more) {
            cp_wait0();
            __syncthreads();   // all MMAs done with bufs; staging complete everywhere
            for (int i = tid; i < BN * 32; i += NT) {
                int row = i >> 5, k4 = i & 31;
                uint32_t off = (uint32_t)(row * 256 + ((k4 * 8) ^ ((row & 7) << 4)));
                float4 kf = *(const float4*)(sm + STK_O + i * 16);
                uint32_t h0, l0, h1, l1;
                split2(kf.x, kf.y, h0, l0); split2(kf.z, kf.w, h1, l1);
                *(uint2*)(sm + KH_O + off) = make_uint2(h0, h1);
                *(uint2*)(sm + KL_O + off) = make_uint2(l0, l1);
                float4 vf = *(const float4*)(sm + STV_O + i * 16);
                split2(vf.x, vf.y, h0, l0); split2(vf.z, vf.w, h1, l1);
                *(uint2*)(sm + VH_O + off) = make_uint2(h0, h1);
                *(uint2*)(sm + VL_O + off) = make_uint2(l0, l1);
            }
            __syncthreads();
        }
    }

    // ---- epilogue ----
    const float inv0 = 1.f / l0r, inv1 = 1.f / l1r;
    #pragma unroll
    for (int n = 0; n < 16; n++) {
        int col = n * 8 + cb;
        *(float2*)(Og + (size_t)r0gl * DDIM + col) = make_float2(o[n][0] * inv0, o[n][1] * inv0);
        *(float2*)(Og + (size_t)r1gl * DDIM + col) = make_float2(o[n][2] * inv1, o[n][3] * inv1);
    }
}

extern "C" void kernel_launch(void* const* d_in, const int* in_sizes, int n_in,
                              void* d_out, int out_size) {
    const float* Q = (const float*)d_in[0];
    const float* K = (const float*)d_in[1];
    const float* V = (const float*)d_in[2];
    float*       O = (float*)d_out;
    int B = in_sizes[0] / (S_LEN * DDIM);
    cudaFuncSetAttribute(attn_hmma, cudaFuncAttributeMaxDynamicSharedMemorySize, SMEM_BYTES);
    dim3 grid(S_LEN / BM, B);
    attn_hmma<<<grid, NT, SMEM_BYTES>>>(Q, K, V, O);
}

// round 7
// speedup vs baseline: 3.1737x; 1.0596x over previous
#include <cuda_runtime.h>
#include <cuda_bf16.h>
#include <stdint.h>
#include <math.h>

#define S_LEN 2048
#define DDIM  128
#define BM 128
#define BN 64
#define NT 256

// double-buffered bf16 tiles: buf s at s*65536, layout KH|KL|VH|VL (16KB each)
#define KH 0
#define KL 16384
#define VH 32768
#define VL 49152
#define STK_O 131072
#define STV_O 163840
#define SMEM_BYTES 196608
// Q bf16 staging (prologue only) overlays buf0
#define QH_O 0
#define QL_O 32768

static __device__ __forceinline__ uint32_t smem_u32(const void* p) {
    uint32_t a;
    asm("{ .reg .u64 t; cvta.to.shared.u64 t, %1; cvt.u32.u64 %0, t; }" : "=r"(a) : "l"(p));
    return a;
}
static __device__ __forceinline__ void ldsm_x4(uint32_t r[4], uint32_t a) {
    asm volatile("ldmatrix.sync.aligned.m8n8.x4.shared.b16 {%0,%1,%2,%3}, [%4];"
                 : "=r"(r[0]), "=r"(r[1]), "=r"(r[2]), "=r"(r[3]) : "r"(a));
}
static __device__ __forceinline__ void ldsm_x2(uint32_t r[2], uint32_t a) {
    asm volatile("ldmatrix.sync.aligned.m8n8.x2.shared.b16 {%0,%1}, [%2];"
                 : "=r"(r[0]), "=r"(r[1]) : "r"(a));
}
static __device__ __forceinline__ void ldsm_x2t(uint32_t r[2], uint32_t a) {
    asm volatile("ldmatrix.sync.aligned.m8n8.x2.trans.shared.b16 {%0,%1}, [%2];"
                 : "=r"(r[0]), "=r"(r[1]) : "r"(a));
}
static __device__ __forceinline__ void mma16816(float c[4], const uint32_t a[4], const uint32_t b[2]) {
    asm volatile("mma.sync.aligned.m16n8k16.row.col.f32.bf16.bf16.f32 "
                 "{%0,%1,%2,%3}, {%4,%5,%6,%7}, {%8,%9}, {%0,%1,%2,%3};"
                 : "+f"(c[0]), "+f"(c[1]), "+f"(c[2]), "+f"(c[3])
                 : "r"(a[0]), "r"(a[1]), "r"(a[2]), "r"(a[3]), "r"(b[0]), "r"(b[1]));
}
static __device__ __forceinline__ void cp16(uint32_t dst, const void* src) {
    asm volatile("cp.async.cg.shared.global [%0], [%1], 16;" :: "r"(dst), "l"(src));
}
static __device__ __forceinline__ void cp_commit() {
    asm volatile("cp.async.commit_group;" ::: "memory");
}
static __device__ __forceinline__ void cp_wait0() {
    asm volatile("cp.async.wait_group 0;" ::: "memory");
}
static __device__ __forceinline__ float ex2(float x) {
    float y;
    asm("ex2.approx.f32 %0, %1;" : "=f"(y) : "f"(x));
    return y;
}
static __device__ __forceinline__ void split2(float x, float y, uint32_t& h, uint32_t& l) {
    __nv_bfloat16 hx = __float2bfloat16_rn(x), hy = __float2bfloat16_rn(y);
    h = ((uint32_t)__bfloat16_as_ushort(hy) << 16) | __bfloat16_as_ushort(hx);
    __nv_bfloat16 lx = __float2bfloat16_rn(x - __bfloat162float(hx));
    __nv_bfloat16 ly = __float2bfloat16_rn(y - __bfloat162float(hy));
    l = ((uint32_t)__bfloat16_as_ushort(ly) << 16) | __bfloat16_as_ushort(lx);
}

__global__ __launch_bounds__(NT, 1)
void attn_hmma(const float* __restrict__ Q, const float* __restrict__ K,
               const float* __restrict__ V, float* __restrict__ O) {
    extern __shared__ char sm[];
    const uint32_t sb = smem_u32(sm);
    const int tid  = threadIdx.x;
    const int lane = tid & 31;
    const int w    = tid >> 5;
    const int qt    = gridDim.x - 1 - blockIdx.x;   // heavy CTAs first
    const int b     = blockIdx.y;
    const int qbase = qt * BM;
    const int ntile = 2 * qt + 2;
    const int m0    = w * 16;

    const float* Qg = Q + (size_t)b * S_LEN * DDIM;
    const float* Kg = K + (size_t)b * S_LEN * DDIM;
    const float* Vg = V + (size_t)b * S_LEN * DDIM;
    float*       Og = O + (size_t)b * S_LEN * DDIM;

    // ldmatrix lane decodes
    const int aR   = m0 + (lane & 15);
    const int aK   = (lane & 16) ? 16 : 0;
    const int aXor = (aR & 7) << 4;
    const int lb   = lane & 15;
    const int bR   = lb & 7;
    const int bK   = (lb & 8) ? 16 : 0;
    const int bXor = bR << 4;
    const int vR   = lb;
    const int vXor = (vR & 7) << 4;

    // ---- stage tile 0 raw K/V (overlaps all Q work) ----
    #pragma unroll
    for (int j = 0; j < 8; j++) {
        int i = tid + j * NT;
        cp16(sb + STK_O + i * 16, (const void*)(Kg + (size_t)i * 4));
        cp16(sb + STV_O + i * 16, (const void*)(Vg + (size_t)i * 4));
    }
    cp_commit();

    // ---- Q -> bf16 smem staging -> registers ----
    for (int i = tid; i < BM * 32; i += NT) {
        int row = i >> 5, k4 = i & 31;
        float4 q = ((const float4*)Qg)[(size_t)(qbase + row) * 32 + k4];
        uint32_t h0, l0, h1, l1;
        split2(q.x, q.y, h0, l0); split2(q.z, q.w, h1, l1);
        uint32_t off = (uint32_t)(row * 256 + ((k4 * 8) ^ ((row & 7) << 4)));
        *(uint2*)(sm + QH_O + off) = make_uint2(h0, h1);
        *(uint2*)(sm + QL_O + off) = make_uint2(l0, l1);
    }
    __syncthreads();
    uint32_t qh[8][4], ql[8][4];
    #pragma unroll
    for (int kk = 0; kk < 8; kk++) {
        ldsm_x4(qh[kk], sb + QH_O + aR * 256 + ((kk * 32 + aK) ^ aXor));
        ldsm_x4(ql[kk], sb + QL_O + aR * 256 + ((kk * 32 + aK) ^ aXor));
    }
    __syncthreads();   // Q staging free; buf0 may be written

    // ---- convert tile 0 into buf0 (own chunks only) ----
    cp_wait0();
    #pragma unroll
    for (int kk = 0; kk < 8; kk++) {
        int i = tid + kk * NT;
        int row = i >> 5, k4 = i & 31;
        uint32_t off = (uint32_t)(row * 256 + ((k4 * 8) ^ ((row & 7) << 4)));
        float4 kf = *(const float4*)(sm + STK_O + i * 16);
        uint32_t h0, l0, h1, l1;
        split2(kf.x, kf.y, h0, l0); split2(kf.z, kf.w, h1, l1);
        *(uint2*)(sm + KH + off) = make_uint2(h0, h1);
        *(uint2*)(sm + KL + off) = make_uint2(l0, l1);
        float4 vf = *(const float4*)(sm + STV_O + i * 16);
        split2(vf.x, vf.y, h0, l0); split2(vf.z, vf.w, h1, l1);
        *(uint2*)(sm + VH + off) = make_uint2(h0, h1);
        *(uint2*)(sm + VL + off) = make_uint2(l0, l1);
    }
    __syncthreads();
    if (ntile > 1) {   // stage tile 1
        #pragma unroll
        for (int j = 0; j < 8; j++) {
            int i = tid + j * NT;
            cp16(sb + STK_O + i * 16, (const void*)(Kg + (size_t)(BN * DDIM + i * 4)));
            cp16(sb + STV_O + i * 16, (const void*)(Vg + (size_t)(BN * DDIM + i * 4)));
        }
        cp_commit();
    }

    float o[16][4];
    #pragma unroll
    for (int n = 0; n < 16; n++)
        #pragma unroll
        for (int i = 0; i < 4; i++) o[n][i] = 0.f;
    float mr0 = -INFINITY, mr1 = -INFINITY, l0r = 0.f, l1r = 0.f;

    const int r0gl = qbase + m0 + (lane >> 2);
    const int r1gl = r0gl + 8;
    const int cb   = (lane & 3) * 2;
    // 1/sqrt(128) * log2(e), folded: softmax runs in base-2 domain
    const float SCALE2 = 0.0883883476483184405f * 1.4426950408889634f;

    for (int t = 0; t < ntile; t++) {
        const int kb = t * BN;
        const bool more = (t + 1 < ntile);
        const char* smA = sm + (size_t)(t & 1) * 65536;
        char*       smB = sm + (size_t)((t + 1) & 1) * 65536;
        const uint32_t bufA = sb + (uint32_t)(t & 1) * 65536;

        if (more) cp_wait0();   // raw tile t+1 fully staged (per-thread groups)
        __syncthreads();        // all warps done reading buf B (tile t-1)

        // ---- S = Q K^T on bufA, interleaved with convert staging -> bufB ----
        float cs[8][4];
        #pragma unroll
        for (int n = 0; n < 8; n++)
            #pragma unroll
            for (int i = 0; i < 4; i++) cs[n][i] = 0.f;

        #pragma unroll
        for (int kk = 0; kk < 8; kk++) {
            if (more) {   // convert one chunk of next tile (own data, no sync needed)
                int i = tid + kk * NT;
                int row = i >> 5, k4 = i & 31;
                uint32_t off = (uint32_t)(row * 256 + ((k4 * 8) ^ ((row & 7) << 4)));
                float4 kf = *(const float4*)(sm + STK_O + i * 16);
                uint32_t h0, l0, h1, l1;
                split2(kf.x, kf.y, h0, l0); split2(kf.z, kf.w, h1, l1);
                *(uint2*)(smB + KH + off) = make_uint2(h0, h1);
                *(uint2*)(smB + KL + off) = make_uint2(l0, l1);
                float4 vf = *(const float4*)(sm + STV_O + i * 16);
                split2(vf.x, vf.y, h0, l0); split2(vf.z, vf.w, h1, l1);
                *(uint2*)(smB + VH + off) = make_uint2(h0, h1);
                *(uint2*)(smB + VL + off) = make_uint2(l0, l1);
            }
            #pragma unroll
            for (int n = 0; n < 8; n++) {
                uint32_t bh[2], bl[2];
                ldsm_x2(bh, bufA + KH + (n * 8 + bR) * 256 + ((kk * 32 + bK) ^ bXor));
                mma16816(cs[n], qh[kk], bh);
                mma16816(cs[n], ql[kk], bh);
                ldsm_x2(bl, bufA + KL + (n * 8 + bR) * 256 + ((kk * 32 + bK) ^ bXor));
                mma16816(cs[n], qh[kk], bl);
            }
        }

        __syncthreads();   // convert reads of staging drained; safe to restage
        if (t + 2 < ntile) {   // stage raw tile t+2
            const float* Kn = Kg + (size_t)(kb + 2 * BN) * DDIM;
            const float* Vn = Vg + (size_t)(kb + 2 * BN) * DDIM;
            #pragma unroll
            for (int j = 0; j < 8; j++) {
                int i = tid + j * NT;
                cp16(sb + STK_O + i * 16, (const void*)(Kn + (size_t)i * 4));
                cp16(sb + STV_O + i * 16, (const void*)(Vn + (size_t)i * 4));
            }
            cp_commit();
        }

        // ---- mask + row max (log2 domain) ----
        float mx0 = -INFINITY, mx1 = -INFINITY;
        if (kb + BN - 1 > qbase + m0) {   // warp-uniform: masking needed
            #pragma unroll
            for (int n = 0; n < 8; n++) {
                int jg = kb + n * 8 + cb;
                float x0 = cs[n][0] * SCALE2; if (jg > r0gl)     x0 = -1.5e9f;
                float x1 = cs[n][1] * SCALE2; if (jg + 1 > r0gl) x1 = -1.5e9f;
                float x2 = cs[n][2] * SCALE2; if (jg > r1gl)     x2 = -1.5e9f;
                float x3 = cs[n][3] * SCALE2; if (jg + 1 > r1gl) x3 = -1.5e9f;
                cs[n][0] = x0; cs[n][1] = x1; cs[n][2] = x2; cs[n][3] = x3;
                mx0 = fmaxf(mx0, fmaxf(x0, x1));
                mx1 = fmaxf(mx1, fmaxf(x2, x3));
            }
        } else {
            #pragma unroll
            for (int n = 0; n < 8; n++) {
                float x0 = cs[n][0] * SCALE2, x1 = cs[n][1] * SCALE2;
                float x2 = cs[n][2] * SCALE2, x3 = cs[n][3] * SCALE2;
                cs[n][0] = x0; cs[n][1] = x1; cs[n][2] = x2; cs[n][3] = x3;
                mx0 = fmaxf(mx0, fmaxf(x0, x1));
                mx1 = fmaxf(mx1, fmaxf(x2, x3));
            }
        }
        mx0 = fmaxf(mx0, __shfl_xor_sync(0xffffffffu, mx0, 1));
        mx0 = fmaxf(mx0, __shfl_xor_sync(0xffffffffu, mx0, 2));
        mx1 = fmaxf(mx1, __shfl_xor_sync(0xffffffffu, mx1, 1));
        mx1 = fmaxf(mx1, __shfl_xor_sync(0xffffffffu, mx1, 2));
        float mn0 = fmaxf(mr0, mx0), mn1 = fmaxf(mr1, mx1);
        float al0 = ex2(mr0 - mn0), al1 = ex2(mr1 - mn1);
        mr0 = mn0; mr1 = mn1;

        #pragma unroll
        for (int n = 0; n < 16; n++) {
            o[n][0] *= al0; o[n][1] *= al0;
            o[n][2] *= al1; o[n][3] *= al1;
        }

        // ---- PV with exp/split fused per k-group (MUFU hides under tensor) ----
        float s0 = 0.f, s1 = 0.f;
        #pragma unroll
        for (int g = 0; g < 4; g++) {
            uint32_t ph[4], pl[4];
            #pragma unroll
            for (int hh = 0; hh < 2; hh++) {
                int n = g * 2 + hh;
                float p0 = ex2(cs[n][0] - mn0);
                float p1 = ex2(cs[n][1] - mn0);
                float p2 = ex2(cs[n][2] - mn1);
                float p3 = ex2(cs[n][3] - mn1);
                s0 += p0 + p1; s1 += p2 + p3;
                split2(p0, p1, ph[hh * 2], pl[hh * 2]);
                split2(p2, p3, ph[hh * 2 + 1], pl[hh * 2 + 1]);
            }
            #pragma unroll
            for (int n = 0; n < 16; n++) {
                uint32_t bh[2], bl[2];
                ldsm_x2t(bh, bufA + VH + (g * 16 + vR) * 256 + ((n * 16) ^ vXor));
                mma16816(o[n], ph, bh);
                mma16816(o[n], pl, bh);
                ldsm_x2t(bl, bufA + VL + (g * 16 + vR) * 256 + ((n * 16) ^ vXor));
                mma16816(o[n], ph, bl);
            }
        }
        s0 += __shfl_xor_sync(0xffffffffu, s0, 1);
        s0 += __shfl_xor_sync(0xffffffffu, s0, 2);
        s1 += __shfl_xor_sync(0xffffffffu, s1, 1);
        s1 += __shfl_xor_sync(0xffffffffu, s1, 2);
        l0r = l0r * al0 + s0;
        l1r = l1r * al1 + s1;
    }

    // ---- epilogue ----
    const float inv0 = 1.f / l0r, inv1 = 1.f / l1r;
    #pragma unroll
    for (int n = 0; n < 16; n++) {
        int col = n * 8 + cb;
        *(float2*)(Og + (size_t)r0gl * DDIM + col) = make_float2(o[n][0] * inv0, o[n][1] * inv0);
        *(float2*)(Og + (size_t)r1gl * DDIM + col) = make_float2(o[n][2] * inv1, o[n][3] * inv1);
    }
}

extern "C" void kernel_launch(void* const* d_in, const int* in_sizes, int n_in,
                              void* d_out, int out_size) {
    const float* Q = (const float*)d_in[0];
    const float* K = (const float*)d_in[1];
    const float* V = (const float*)d_in[2];
    float*       O = (float*)d_out;
    int B = in_sizes[0] / (S_LEN * DDIM);
    cudaFuncSetAttribute(attn_hmma, cudaFuncAttributeMaxDynamicSharedMemorySize, SMEM_BYTES);
    dim3 grid(S_LEN / BM, B);
    attn_hmma<<<grid, NT, SMEM_BYTES>>>(Q, K, V, O);
}